// round 2
// baseline (speedup 1.0000x reference)
#include <cuda_runtime.h>

#define DT_C 0.02f
#define GRAV_C 10.0f
#define THRUST_C 6.0f
#define TORQUE_C 1.0f

__global__ __launch_bounds__(128, 8)
void ekf_kernel(const float* __restrict__ z, const float* __restrict__ u,
                const float* __restrict__ xprev, const float* __restrict__ Pprev,
                const float* __restrict__ qld, const float* __restrict__ qod,
                const float* __restrict__ rld, const float* __restrict__ rod,
                float* __restrict__ out_x, float* __restrict__ out_P, int B) {
    __shared__ float sQ[36];
    __shared__ float sR[9];

    // Threads 0..35 build Q = L L^T + 1e-6 I, threads 36..44 build R likewise.
    // L[i][k] = qod[i*(i-1)/2 + k] (k<i), exp(qld[i]) (k==i), 0 (k>i).
    int t = threadIdx.x;
    if (t < 36) {
        int i = t / 6, j = t % 6;
        float acc = (i == j) ? 1e-6f : 0.0f;
        #pragma unroll
        for (int k = 0; k < 6; k++) {
            float Lik = (k < i) ? qod[i * (i - 1) / 2 + k] : ((k == i) ? expf(qld[i]) : 0.0f);
            float Ljk = (k < j) ? qod[j * (j - 1) / 2 + k] : ((k == j) ? expf(qld[j]) : 0.0f);
            acc += Lik * Ljk;
        }
        sQ[t] = acc;
    } else if (t < 45) {
        int t2 = t - 36;
        int i = t2 / 3, j = t2 % 3;
        float acc = (i == j) ? 1e-6f : 0.0f;
        #pragma unroll
        for (int k = 0; k < 3; k++) {
            float Lik = (k < i) ? rod[i * (i - 1) / 2 + k] : ((k == i) ? expf(rld[i]) : 0.0f);
            float Ljk = (k < j) ? rod[j * (j - 1) / 2 + k] : ((k == j) ? expf(rld[j]) : 0.0f);
            acc += Lik * Ljk;
        }
        sR[t2] = acc;
    }
    __syncthreads();

    int b = blockIdx.x * blockDim.x + threadIdx.x;
    if (b >= B) return;

    // ---- Load P_prev (36 floats, 9x float4 contiguous) ----
    float Pf[36];
    {
        const float4* p4 = reinterpret_cast<const float4*>(Pprev + (size_t)b * 36);
        #pragma unroll
        for (int i = 0; i < 9; i++) {
            float4 v = p4[i];
            Pf[4 * i + 0] = v.x; Pf[4 * i + 1] = v.y;
            Pf[4 * i + 2] = v.z; Pf[4 * i + 3] = v.w;
        }
    }
#define Pm(i, j) Pf[(i) * 6 + (j)]

    // ---- Load state, control, observation ----
    float px, py, vx, vy, th, om;
    {
        const float2* x2 = reinterpret_cast<const float2*>(xprev + (size_t)b * 6);
        float2 a = x2[0], bb = x2[1], cc = x2[2];
        px = a.x; py = a.y; vx = bb.x; vy = bb.y; th = cc.x; om = cc.y;
    }
    float2 uu = reinterpret_cast<const float2*>(u)[b];
    float z0 = z[(size_t)b * 3 + 0];
    float z1 = z[(size_t)b * 3 + 1];
    float z2 = z[(size_t)b * 3 + 2];

    // ---- Dynamics + Jacobian column-4 coefficients ----
    float mp = fminf(fmaxf(uu.x, 0.0f), 1.0f);
    float s, c;
    __sincosf(th, &s, &c);
    float Tm = THRUST_C * mp;
    float nvx = vx + (-Tm * s) * DT_C;
    float nvy = vy + (Tm * c - GRAV_C) * DT_C;
    float nom = om + (TORQUE_C * uu.y) * DT_C;
    float npx = px + nvx * DT_C;
    float npy = py + nvy * DT_C;
    float nth = th + nom * DT_C;

    float a2 = -Tm * c * DT_C;       // F[2][4]
    float a3 = -Tm * s * DT_C;       // F[3][4]
    float a0 = a2 * DT_C;            // F[0][4]
    float a1 = a3 * DT_C;            // F[1][4]

    // ---- P_pred = F P F^T + Q ; F = I + sparse. In-place row ops then col ops. ----
    #pragma unroll
    for (int j = 0; j < 6; j++) {
        Pm(0, j) += DT_C * Pm(2, j) + a0 * Pm(4, j);
        Pm(1, j) += DT_C * Pm(3, j) + a1 * Pm(4, j);
        Pm(2, j) += a2 * Pm(4, j);
        Pm(3, j) += a3 * Pm(4, j);
        Pm(4, j) += DT_C * Pm(5, j);
    }
    #pragma unroll
    for (int i = 0; i < 6; i++) {
        Pm(i, 0) += DT_C * Pm(i, 2) + a0 * Pm(i, 4);
        Pm(i, 1) += DT_C * Pm(i, 3) + a1 * Pm(i, 4);
        Pm(i, 2) += a2 * Pm(i, 4);
        Pm(i, 3) += a3 * Pm(i, 4);
        Pm(i, 4) += DT_C * Pm(i, 5);
    }

    // ---- Keep only upper triangle (symmetric), fold in Q ----
    // up[] index for (i,j), i<=j: off[i] + j, off = {0,5,9,12,14,15} - i => use table
    float up[21];
    {
        int k = 0;
        #pragma unroll
        for (int i = 0; i < 6; i++)
            #pragma unroll
            for (int j = i; j < 6; j++) {
                up[k] = Pm(i, j) + sQ[i * 6 + j];
                k++;
            }
    }
#undef Pm
    // Accessor for symmetric P_pred: U(i,j) valid for i<=j
#define UIDX(i, j) ((i) * 6 - (i) * ((i) + 1) / 2 + (j))
#define US(i, j) ((i) <= (j) ? up[UIDX(i, j)] : up[UIDX(j, i)])

    // ---- S = P_pred[(0,1,4),(0,1,4)] + R ; symmetric 3x3 inverse ----
    float S00 = US(0, 0) + sR[0];
    float S01 = US(0, 1) + sR[1];
    float S02 = US(0, 4) + sR[2];
    float S11 = US(1, 1) + sR[4];
    float S12 = US(1, 4) + sR[5];
    float S22 = US(4, 4) + sR[8];

    float i00 = S11 * S22 - S12 * S12;
    float i01 = S02 * S12 - S01 * S22;
    float i02 = S01 * S12 - S02 * S11;
    float i11 = S00 * S22 - S02 * S02;
    float i12 = S01 * S02 - S00 * S12;
    float i22 = S00 * S11 - S01 * S01;
    float invdet = 1.0f / (S00 * i00 + S01 * i01 + S02 * i02);
    i00 *= invdet; i01 *= invdet; i02 *= invdet;
    i11 *= invdet; i12 *= invdet; i22 *= invdet;

    // ---- hp_k = (P[0][k], P[1][k], P[4][k]); K[k] = Si * hp_k (Si symmetric) ----
    float K[6][3];
    float hp[6][3];
    #pragma unroll
    for (int k = 0; k < 6; k++) {
        float h0 = US(0, k), h1 = US(1, k), h2 = US(4, k);
        hp[k][0] = h0; hp[k][1] = h1; hp[k][2] = h2;
        K[k][0] = h0 * i00 + h1 * i01 + h2 * i02;
        K[k][1] = h0 * i01 + h1 * i11 + h2 * i12;
        K[k][2] = h0 * i02 + h1 * i12 + h2 * i22;
    }

    // ---- x_upd = x_pred + K y ----
    float y0 = z0 - npx, y1 = z1 - npy, y2 = z2 - nth;
    float xpred[6] = {npx, npy, nvx, nvy, nth, nom};
    float xout[6];
    #pragma unroll
    for (int i = 0; i < 6; i++)
        xout[i] = xpred[i] + K[i][0] * y0 + K[i][1] * y1 + K[i][2] * y2;

    // ---- P_upd = P_pred - K (H P_pred)  (optimal-gain form; symmetric) ----
    // P_upd[i][j] = up[i,j] - K[i]·hp_j ; compute upper triangle in place.
    {
        int k = 0;
        #pragma unroll
        for (int i = 0; i < 6; i++)
            #pragma unroll
            for (int j = i; j < 6; j++) {
                up[k] -= K[i][0] * hp[j][0] + K[i][1] * hp[j][1] + K[i][2] * hp[j][2];
                k++;
            }
    }

    // ---- Stores (mirror symmetric P_upd to full 6x6) ----
    {
        float2* ox2 = reinterpret_cast<float2*>(out_x + (size_t)b * 6);
        ox2[0] = make_float2(xout[0], xout[1]);
        ox2[1] = make_float2(xout[2], xout[3]);
        ox2[2] = make_float2(xout[4], xout[5]);

        float Pu[36];
        #pragma unroll
        for (int i = 0; i < 6; i++)
            #pragma unroll
            for (int j = i; j < 6; j++) {
                float v = up[UIDX(i, j)];
                Pu[i * 6 + j] = v;
                Pu[j * 6 + i] = v;
            }
        float4* op4 = reinterpret_cast<float4*>(out_P + (size_t)b * 36);
        #pragma unroll
        for (int i = 0; i < 9; i++)
            op4[i] = make_float4(Pu[4 * i + 0], Pu[4 * i + 1], Pu[4 * i + 2], Pu[4 * i + 3]);
    }
#undef US
#undef UIDX
}

extern "C" void kernel_launch(void* const* d_in, const int* in_sizes, int n_in,
                              void* d_out, int out_size) {
    const float* z   = (const float*)d_in[0];
    const float* u   = (const float*)d_in[1];
    const float* xp  = (const float*)d_in[2];
    const float* Pp  = (const float*)d_in[3];
    const float* qld = (const float*)d_in[4];
    const float* qod = (const float*)d_in[5];
    const float* rld = (const float*)d_in[6];
    const float* rod = (const float*)d_in[7];

    int B = in_sizes[0] / 3;
    float* out_x = (float*)d_out;
    float* out_P = out_x + (size_t)B * 6;

    ekf_kernel<<<(B + 127) / 128, 128>>>(z, u, xp, Pp, qld, qod, rld, rod, out_x, out_P, B);
}

// round 3
// speedup vs baseline: 1.2354x; 1.2354x over previous
#include <cuda_runtime.h>
#include <cstdint>

#define DT_C 0.02f
#define GRAV_C 10.0f
#define THRUST_C 6.0f
#define TORQUE_C 1.0f

__device__ __forceinline__ void cp_async16(uint32_t smem_dst, const void* gmem_src) {
    asm volatile("cp.async.cg.shared.global [%0], [%1], 16;"
                 :: "r"(smem_dst), "l"(gmem_src) : "memory");
}

__global__ __launch_bounds__(128, 8)
void ekf_kernel(const float* __restrict__ z, const float* __restrict__ u,
                const float* __restrict__ xprev, const float* __restrict__ Pprev,
                const float* __restrict__ qld, const float* __restrict__ qod,
                const float* __restrict__ rld, const float* __restrict__ rod,
                float* __restrict__ out_x, float* __restrict__ out_P, int B) {
    __shared__ float4 sP[1152];     // 128 threads x 9 float4 = 18432 B
    __shared__ float4 sX4[192];     // 128 x 6 floats = 3072 B
    __shared__ float sQ[36];
    __shared__ float sR[9];
    float* sX = reinterpret_cast<float*>(sX4);

    int t = threadIdx.x;
    size_t b0 = (size_t)blockIdx.x * 128;
    int b = (int)b0 + t;
    bool fullblock = (b0 + 128 <= (size_t)B);

    // ---- Kick off coalesced async staging of P_prev for this block ----
    if (fullblock) {
        const float4* Pg = reinterpret_cast<const float4*>(Pprev) + b0 * 9;
        uint32_t sbase = (uint32_t)__cvta_generic_to_shared(sP);
        #pragma unroll
        for (int k = 0; k < 9; k++)
            cp_async16(sbase + (uint32_t)(t + k * 128) * 16u, Pg + t + k * 128);
        asm volatile("cp.async.commit_group;" ::: "memory");
    }

    // ---- Build Q = L L^T + 1e-6 I (threads 0..35) and R (36..44) ----
    if (t < 36) {
        int i = t / 6, j = t % 6;
        float acc = (i == j) ? 1e-6f : 0.0f;
        #pragma unroll
        for (int k = 0; k < 6; k++) {
            float Lik = (k < i) ? qod[i * (i - 1) / 2 + k] : ((k == i) ? expf(qld[i]) : 0.0f);
            float Ljk = (k < j) ? qod[j * (j - 1) / 2 + k] : ((k == j) ? expf(qld[j]) : 0.0f);
            acc += Lik * Ljk;
        }
        sQ[t] = acc;
    } else if (t < 45) {
        int t2 = t - 36;
        int i = t2 / 3, j = t2 % 3;
        float acc = (i == j) ? 1e-6f : 0.0f;
        #pragma unroll
        for (int k = 0; k < 3; k++) {
            float Lik = (k < i) ? rod[i * (i - 1) / 2 + k] : ((k == i) ? expf(rld[i]) : 0.0f);
            float Ljk = (k < j) ? rod[j * (j - 1) / 2 + k] : ((k == j) ? expf(rld[j]) : 0.0f);
            acc += Lik * Ljk;
        }
        sR[t2] = acc;
    }

    // ---- Small per-thread loads (overlap with cp.async in flight) ----
    float px = 0, py = 0, vx = 0, vy = 0, th = 0, om = 0;
    float u0 = 0, u1 = 0, z0 = 0, z1 = 0, z2 = 0;
    bool active = (b < B);
    if (active) {
        const float2* x2 = reinterpret_cast<const float2*>(xprev + (size_t)b * 6);
        float2 a = x2[0], bb = x2[1], cc = x2[2];
        px = a.x; py = a.y; vx = bb.x; vy = bb.y; th = cc.x; om = cc.y;
        float2 uu = reinterpret_cast<const float2*>(u)[b];
        u0 = uu.x; u1 = uu.y;
        z0 = z[(size_t)b * 3 + 0];
        z1 = z[(size_t)b * 3 + 1];
        z2 = z[(size_t)b * 3 + 2];
    }

    // ---- Dynamics + Jacobian coefficients ----
    float mp = fminf(fmaxf(u0, 0.0f), 1.0f);
    float s, c;
    __sincosf(th, &s, &c);
    float Tm = THRUST_C * mp;
    float nvx = vx + (-Tm * s) * DT_C;
    float nvy = vy + (Tm * c - GRAV_C) * DT_C;
    float nom = om + (TORQUE_C * u1) * DT_C;
    float npx = px + nvx * DT_C;
    float npy = py + nvy * DT_C;
    float nth = th + nom * DT_C;

    float a2 = -Tm * c * DT_C;   // F[2][4]
    float a3 = -Tm * s * DT_C;   // F[3][4]
    float a0 = a2 * DT_C;        // F[0][4]
    float a1 = a3 * DT_C;        // F[1][4]

    if (fullblock)
        asm volatile("cp.async.wait_group 0;" ::: "memory");
    __syncthreads();   // Q/R visible + staged P visible

    if (!active) return;  // only possible in a partial block (no more syncs on that path)

    // ---- Fetch my P_prev: staged (conflict-free LDS.128) or direct fallback ----
    float Pf[36];
    if (fullblock) {
        #pragma unroll
        for (int i = 0; i < 9; i++) {
            float4 v = sP[t * 9 + i];
            Pf[4 * i + 0] = v.x; Pf[4 * i + 1] = v.y;
            Pf[4 * i + 2] = v.z; Pf[4 * i + 3] = v.w;
        }
    } else {
        const float4* p4 = reinterpret_cast<const float4*>(Pprev + (size_t)b * 36);
        #pragma unroll
        for (int i = 0; i < 9; i++) {
            float4 v = p4[i];
            Pf[4 * i + 0] = v.x; Pf[4 * i + 1] = v.y;
            Pf[4 * i + 2] = v.z; Pf[4 * i + 3] = v.w;
        }
    }
#define Pm(i, j) Pf[(i) * 6 + (j)]

    // ---- P_pred = F P F^T + Q ; F = I + sparse. Row ops then col ops, in place. ----
    #pragma unroll
    for (int j = 0; j < 6; j++) {
        Pm(0, j) += DT_C * Pm(2, j) + a0 * Pm(4, j);
        Pm(1, j) += DT_C * Pm(3, j) + a1 * Pm(4, j);
        Pm(2, j) += a2 * Pm(4, j);
        Pm(3, j) += a3 * Pm(4, j);
        Pm(4, j) += DT_C * Pm(5, j);
    }
    #pragma unroll
    for (int i = 0; i < 6; i++) {
        Pm(i, 0) += DT_C * Pm(i, 2) + a0 * Pm(i, 4);
        Pm(i, 1) += DT_C * Pm(i, 3) + a1 * Pm(i, 4);
        Pm(i, 2) += a2 * Pm(i, 4);
        Pm(i, 3) += a3 * Pm(i, 4);
        Pm(i, 4) += DT_C * Pm(i, 5);
    }

    // ---- Upper triangle of P_pred + Q ----
    float up[21];
    {
        int k = 0;
        #pragma unroll
        for (int i = 0; i < 6; i++)
            #pragma unroll
            for (int j = i; j < 6; j++) {
                up[k] = Pm(i, j) + sQ[i * 6 + j];
                k++;
            }
    }
#undef Pm
#define UIDX(i, j) ((i) * 6 - (i) * ((i) + 1) / 2 + (j))
#define US(i, j) ((i) <= (j) ? up[UIDX(i, j)] : up[UIDX(j, i)])

    // ---- S = P_pred[(0,1,4),(0,1,4)] + R ; symmetric 3x3 inverse ----
    float S00 = US(0, 0) + sR[0];
    float S01 = US(0, 1) + sR[1];
    float S02 = US(0, 4) + sR[2];
    float S11 = US(1, 1) + sR[4];
    float S12 = US(1, 4) + sR[5];
    float S22 = US(4, 4) + sR[8];

    float i00 = S11 * S22 - S12 * S12;
    float i01 = S02 * S12 - S01 * S22;
    float i02 = S01 * S12 - S02 * S11;
    float i11 = S00 * S22 - S02 * S02;
    float i12 = S01 * S02 - S00 * S12;
    float i22 = S00 * S11 - S01 * S01;
    float invdet = 1.0f / (S00 * i00 + S01 * i01 + S02 * i02);
    i00 *= invdet; i01 *= invdet; i02 *= invdet;
    i11 *= invdet; i12 *= invdet; i22 *= invdet;

    // ---- K[k] = Si * (P[0][k], P[1][k], P[4][k]) ----
    float K[6][3];
    #pragma unroll
    for (int k = 0; k < 6; k++) {
        float h0 = US(0, k), h1 = US(1, k), h2 = US(4, k);
        K[k][0] = h0 * i00 + h1 * i01 + h2 * i02;
        K[k][1] = h0 * i01 + h1 * i11 + h2 * i12;
        K[k][2] = h0 * i02 + h1 * i12 + h2 * i22;
    }

    // ---- x_upd ----
    float y0 = z0 - npx, y1 = z1 - npy, y2 = z2 - nth;
    float xpred[6] = {npx, npy, nvx, nvy, nth, nom};
    float xout[6];
    #pragma unroll
    for (int i = 0; i < 6; i++)
        xout[i] = xpred[i] + K[i][0] * y0 + K[i][1] * y1 + K[i][2] * y2;

    // ---- P_upd = P_pred - K (H P_pred), upper triangle, computed into Pu full ----
    float Pu[36];
    #pragma unroll
    for (int i = 0; i < 6; i++)
        #pragma unroll
        for (int j = i; j < 6; j++) {
            float v = US(i, j)
                - K[i][0] * US(0, j) - K[i][1] * US(1, j) - K[i][2] * US(4, j);
            Pu[i * 6 + j] = v;
            Pu[j * 6 + i] = v;
        }
#undef US
#undef UIDX

    // ---- Stores ----
    if (fullblock) {
        // stage into smem (conflict-free STS.128 / minor 2-way on sX), then coalesced STG
        #pragma unroll
        for (int i = 0; i < 9; i++)
            sP[t * 9 + i] = make_float4(Pu[4 * i], Pu[4 * i + 1], Pu[4 * i + 2], Pu[4 * i + 3]);
        #pragma unroll
        for (int i = 0; i < 6; i++)
            sX[t * 6 + i] = xout[i];
        __syncthreads();

        float4* Po = reinterpret_cast<float4*>(out_P) + b0 * 9;
        #pragma unroll
        for (int k = 0; k < 9; k++)
            Po[t + k * 128] = sP[t + k * 128];

        float4* Xo = reinterpret_cast<float4*>(out_x + b0 * 6);
        Xo[t] = sX4[t];
        if (t < 64) Xo[128 + t] = sX4[128 + t];
    } else {
        float2* ox2 = reinterpret_cast<float2*>(out_x + (size_t)b * 6);
        ox2[0] = make_float2(xout[0], xout[1]);
        ox2[1] = make_float2(xout[2], xout[3]);
        ox2[2] = make_float2(xout[4], xout[5]);
        float4* op4 = reinterpret_cast<float4*>(out_P + (size_t)b * 36);
        #pragma unroll
        for (int i = 0; i < 9; i++)
            op4[i] = make_float4(Pu[4 * i], Pu[4 * i + 1], Pu[4 * i + 2], Pu[4 * i + 3]);
    }
}

extern "C" void kernel_launch(void* const* d_in, const int* in_sizes, int n_in,
                              void* d_out, int out_size) {
    const float* z   = (const float*)d_in[0];
    const float* u   = (const float*)d_in[1];
    const float* xp  = (const float*)d_in[2];
    const float* Pp  = (const float*)d_in[3];
    const float* qld = (const float*)d_in[4];
    const float* qod = (const float*)d_in[5];
    const float* rld = (const float*)d_in[6];
    const float* rod = (const float*)d_in[7];

    int B = in_sizes[0] / 3;
    float* out_x = (float*)d_out;
    float* out_P = out_x + (size_t)B * 6;

    ekf_kernel<<<(B + 127) / 128, 128>>>(z, u, xp, Pp, qld, qod, rld, rod, out_x, out_P, B);
}

// round 4
// speedup vs baseline: 1.2988x; 1.0513x over previous
#include <cuda_runtime.h>
#include <cstdint>

#define DT_C 0.02f
#define GRAV_C 10.0f
#define THRUST_C 6.0f
#define TORQUE_C 1.0f
#define TPB 128

__device__ __forceinline__ void cp_async16(uint32_t smem_dst, const void* gmem_src) {
    asm volatile("cp.async.cg.shared.global [%0], [%1], 16;"
                 :: "r"(smem_dst), "l"(gmem_src) : "memory");
}
__device__ __forceinline__ void cp_commit() {
    asm volatile("cp.async.commit_group;" ::: "memory");
}

__global__ __launch_bounds__(TPB, 4)
void ekf_kernel(const float* __restrict__ z, const float* __restrict__ u,
                const float* __restrict__ xprev, const float* __restrict__ Pprev,
                const float* __restrict__ qld, const float* __restrict__ qod,
                const float* __restrict__ rld, const float* __restrict__ rod,
                float* __restrict__ out_x, float* __restrict__ out_P, int B) {
    __shared__ float4 sP[2][TPB * 9];        // 36864 B
    __shared__ float4 sXs[2][TPB * 6 / 4];   // 6144 B
    __shared__ float4 sZs[2][TPB * 3 / 4];   // 3072 B
    __shared__ float4 sUs[2][TPB * 2 / 4];   // 2048 B
    __shared__ float sQ[36];
    __shared__ float sR[9];

    const int t = threadIdx.x;
    const int G = gridDim.x;
    const int bid = blockIdx.x;
    const int ntot = (B + TPB - 1) / TPB;
    const int nt = (ntot > bid) ? ((ntot - bid + G - 1) / G) : 0;

    // ---- Build Q = L L^T + 1e-6 I (threads 0..35) and R (36..44), once per CTA ----
    if (t < 36) {
        int i = t / 6, j = t % 6;
        float acc = (i == j) ? 1e-6f : 0.0f;
        #pragma unroll
        for (int k = 0; k < 6; k++) {
            float Lik = (k < i) ? qod[i * (i - 1) / 2 + k] : ((k == i) ? expf(qld[i]) : 0.0f);
            float Ljk = (k < j) ? qod[j * (j - 1) / 2 + k] : ((k == j) ? expf(qld[j]) : 0.0f);
            acc += Lik * Ljk;
        }
        sQ[t] = acc;
    } else if (t < 45) {
        int t2 = t - 36;
        int i = t2 / 3, j = t2 % 3;
        float acc = (i == j) ? 1e-6f : 0.0f;
        #pragma unroll
        for (int k = 0; k < 3; k++) {
            float Lik = (k < i) ? rod[i * (i - 1) / 2 + k] : ((k == i) ? expf(rld[i]) : 0.0f);
            float Ljk = (k < j) ? rod[j * (j - 1) / 2 + k] : ((k == j) ? expf(rld[j]) : 0.0f);
            acc += Lik * Ljk;
        }
        sR[t2] = acc;
    }

    if (nt == 0) return;

    auto issue_tile = [&](int k, int p) {
        int tile = bid + k * G;
        size_t base = (size_t)tile * TPB;
        if (base + TPB <= (size_t)B) {   // full tile: coalesced staging
            const float4* Pg = reinterpret_cast<const float4*>(Pprev) + base * 9;
            uint32_t sb = (uint32_t)__cvta_generic_to_shared(&sP[p][0]);
            #pragma unroll
            for (int kk = 0; kk < 9; kk++)
                cp_async16(sb + (uint32_t)(t + kk * TPB) * 16u, Pg + t + kk * TPB);
            const float4* Xg = reinterpret_cast<const float4*>(xprev + base * 6);
            uint32_t sx = (uint32_t)__cvta_generic_to_shared(&sXs[p][0]);
            cp_async16(sx + (uint32_t)t * 16u, Xg + t);
            if (t < 64) cp_async16(sx + (uint32_t)(TPB + t) * 16u, Xg + TPB + t);
            const float4* Zg = reinterpret_cast<const float4*>(z + base * 3);
            uint32_t sz = (uint32_t)__cvta_generic_to_shared(&sZs[p][0]);
            if (t < 96) cp_async16(sz + (uint32_t)t * 16u, Zg + t);
            const float4* Ug = reinterpret_cast<const float4*>(u + base * 2);
            uint32_t su = (uint32_t)__cvta_generic_to_shared(&sUs[p][0]);
            if (t < 64) cp_async16(su + (uint32_t)t * 16u, Ug + t);
        }
    };

    // ---- Prologue: prefetch first two tiles ----
    issue_tile(0, 0);
    cp_commit();
    if (nt > 1) issue_tile(1, 1);
    cp_commit();   // possibly empty; positional wait semantics keep numbering consistent

    for (int k = 0; k < nt; k++) {
        int p = k & 1;
        int tile = bid + k * G;
        size_t base = (size_t)tile * TPB;
        bool full = (base + TPB <= (size_t)B);
        int b = (int)base + t;
        bool active = (b < B);

        if (k + 1 < nt) asm volatile("cp.async.wait_group 1;" ::: "memory");
        else            asm volatile("cp.async.wait_group 0;" ::: "memory");
        __syncthreads();

        // ---- Gather inputs ----
        float Pf[36];
        float px = 0, py = 0, vx = 0, vy = 0, th = 0, om = 0;
        float u0 = 0, u1 = 0, z0 = 0, z1 = 0, z2 = 0;
        if (full) {
            #pragma unroll
            for (int i = 0; i < 9; i++) {
                float4 v = sP[p][t * 9 + i];
                Pf[4 * i + 0] = v.x; Pf[4 * i + 1] = v.y;
                Pf[4 * i + 2] = v.z; Pf[4 * i + 3] = v.w;
            }
            const float2* x2 = reinterpret_cast<const float2*>(&sXs[p][0]);
            float2 a = x2[3 * t], bb = x2[3 * t + 1], cc = x2[3 * t + 2];
            px = a.x; py = a.y; vx = bb.x; vy = bb.y; th = cc.x; om = cc.y;
            const float* zf = reinterpret_cast<const float*>(&sZs[p][0]);
            z0 = zf[3 * t]; z1 = zf[3 * t + 1]; z2 = zf[3 * t + 2];
            const float2* u2 = reinterpret_cast<const float2*>(&sUs[p][0]);
            float2 uu = u2[t];
            u0 = uu.x; u1 = uu.y;
        } else if (active) {
            const float4* p4 = reinterpret_cast<const float4*>(Pprev + (size_t)b * 36);
            #pragma unroll
            for (int i = 0; i < 9; i++) {
                float4 v = p4[i];
                Pf[4 * i + 0] = v.x; Pf[4 * i + 1] = v.y;
                Pf[4 * i + 2] = v.z; Pf[4 * i + 3] = v.w;
            }
            const float2* x2 = reinterpret_cast<const float2*>(xprev + (size_t)b * 6);
            float2 a = x2[0], bb = x2[1], cc = x2[2];
            px = a.x; py = a.y; vx = bb.x; vy = bb.y; th = cc.x; om = cc.y;
            float2 uu = reinterpret_cast<const float2*>(u)[b];
            u0 = uu.x; u1 = uu.y;
            z0 = z[(size_t)b * 3 + 0];
            z1 = z[(size_t)b * 3 + 1];
            z2 = z[(size_t)b * 3 + 2];
        } else {
            #pragma unroll
            for (int i = 0; i < 36; i++) Pf[i] = 0.0f;
        }
#define Pm(i, j) Pf[(i) * 6 + (j)]

        // ---- Dynamics + Jacobian coefficients ----
        float mp = fminf(fmaxf(u0, 0.0f), 1.0f);
        float s, c;
        __sincosf(th, &s, &c);
        float Tm = THRUST_C * mp;
        float nvx = vx + (-Tm * s) * DT_C;
        float nvy = vy + (Tm * c - GRAV_C) * DT_C;
        float nom = om + (TORQUE_C * u1) * DT_C;
        float npx = px + nvx * DT_C;
        float npy = py + nvy * DT_C;
        float nth = th + nom * DT_C;

        float a2 = -Tm * c * DT_C;   // F[2][4]
        float a3 = -Tm * s * DT_C;   // F[3][4]
        float a0 = a2 * DT_C;        // F[0][4]
        float a1 = a3 * DT_C;        // F[1][4]

        // ---- P_pred = F P F^T + Q (sparse F: row ops then col ops, in place) ----
        #pragma unroll
        for (int j = 0; j < 6; j++) {
            Pm(0, j) += DT_C * Pm(2, j) + a0 * Pm(4, j);
            Pm(1, j) += DT_C * Pm(3, j) + a1 * Pm(4, j);
            Pm(2, j) += a2 * Pm(4, j);
            Pm(3, j) += a3 * Pm(4, j);
            Pm(4, j) += DT_C * Pm(5, j);
        }
        #pragma unroll
        for (int i = 0; i < 6; i++) {
            Pm(i, 0) += DT_C * Pm(i, 2) + a0 * Pm(i, 4);
            Pm(i, 1) += DT_C * Pm(i, 3) + a1 * Pm(i, 4);
            Pm(i, 2) += a2 * Pm(i, 4);
            Pm(i, 3) += a3 * Pm(i, 4);
            Pm(i, 4) += DT_C * Pm(i, 5);
        }

        // ---- Upper triangle of P_pred + Q ----
        float up[21];
        {
            int kk = 0;
            #pragma unroll
            for (int i = 0; i < 6; i++)
                #pragma unroll
                for (int j = i; j < 6; j++) {
                    up[kk] = Pm(i, j) + sQ[i * 6 + j];
                    kk++;
                }
        }
#undef Pm
#define UIDX(i, j) ((i) * 6 - (i) * ((i) + 1) / 2 + (j))
#define US(i, j) ((i) <= (j) ? up[UIDX(i, j)] : up[UIDX(j, i)])

        // ---- S = P_pred[(0,1,4),(0,1,4)] + R ; symmetric 3x3 inverse ----
        float S00 = US(0, 0) + sR[0];
        float S01 = US(0, 1) + sR[1];
        float S02 = US(0, 4) + sR[2];
        float S11 = US(1, 1) + sR[4];
        float S12 = US(1, 4) + sR[5];
        float S22 = US(4, 4) + sR[8];

        float i00 = S11 * S22 - S12 * S12;
        float i01 = S02 * S12 - S01 * S22;
        float i02 = S01 * S12 - S02 * S11;
        float i11 = S00 * S22 - S02 * S02;
        float i12 = S01 * S02 - S00 * S12;
        float i22 = S00 * S11 - S01 * S01;
        float invdet = 1.0f / (S00 * i00 + S01 * i01 + S02 * i02);
        i00 *= invdet; i01 *= invdet; i02 *= invdet;
        i11 *= invdet; i12 *= invdet; i22 *= invdet;

        // ---- K[k] = Si * (P[0][k], P[1][k], P[4][k]) ----
        float K[6][3];
        #pragma unroll
        for (int kk = 0; kk < 6; kk++) {
            float h0 = US(0, kk), h1 = US(1, kk), h2 = US(4, kk);
            K[kk][0] = h0 * i00 + h1 * i01 + h2 * i02;
            K[kk][1] = h0 * i01 + h1 * i11 + h2 * i12;
            K[kk][2] = h0 * i02 + h1 * i12 + h2 * i22;
        }

        // ---- x_upd ----
        float y0 = z0 - npx, y1 = z1 - npy, y2 = z2 - nth;
        float xpred[6] = {npx, npy, nvx, nvy, nth, nom};
        float xout[6];
        #pragma unroll
        for (int i = 0; i < 6; i++)
            xout[i] = xpred[i] + K[i][0] * y0 + K[i][1] * y1 + K[i][2] * y2;

        // ---- P_upd = P_pred - K (H P_pred), symmetric ----
        float Pu[36];
        #pragma unroll
        for (int i = 0; i < 6; i++)
            #pragma unroll
            for (int j = i; j < 6; j++) {
                float v = US(i, j)
                    - K[i][0] * US(0, j) - K[i][1] * US(1, j) - K[i][2] * US(4, j);
                Pu[i * 6 + j] = v;
                Pu[j * 6 + i] = v;
            }
#undef US
#undef UIDX

        // ---- Stores ----
        if (full) {
            // stage into the just-consumed buffer (per-thread regions), then coalesced STG
            #pragma unroll
            for (int i = 0; i < 9; i++)
                sP[p][t * 9 + i] = make_float4(Pu[4 * i], Pu[4 * i + 1], Pu[4 * i + 2], Pu[4 * i + 3]);
            float* sXf = reinterpret_cast<float*>(&sXs[p][0]);
            #pragma unroll
            for (int i = 0; i < 6; i++) sXf[t * 6 + i] = xout[i];
            __syncthreads();

            float4* Po = reinterpret_cast<float4*>(out_P) + base * 9;
            #pragma unroll
            for (int kk = 0; kk < 9; kk++)
                Po[t + kk * TPB] = sP[p][t + kk * TPB];
            float4* Xo = reinterpret_cast<float4*>(out_x + base * 6);
            Xo[t] = sXs[p][t];
            if (t < 64) Xo[TPB + t] = sXs[p][TPB + t];
            __syncthreads();   // LDS-for-STG complete before buffer p is re-prefetched
        } else if (active) {
            float2* ox2 = reinterpret_cast<float2*>(out_x + (size_t)b * 6);
            ox2[0] = make_float2(xout[0], xout[1]);
            ox2[1] = make_float2(xout[2], xout[3]);
            ox2[2] = make_float2(xout[4], xout[5]);
            float4* op4 = reinterpret_cast<float4*>(out_P + (size_t)b * 36);
            #pragma unroll
            for (int i = 0; i < 9; i++)
                op4[i] = make_float4(Pu[4 * i], Pu[4 * i + 1], Pu[4 * i + 2], Pu[4 * i + 3]);
        }

        // ---- Prefetch tile k+2 into buffer p ----
        if (k + 2 < nt) issue_tile(k + 2, p);
        cp_commit();
    }
}

extern "C" void kernel_launch(void* const* d_in, const int* in_sizes, int n_in,
                              void* d_out, int out_size) {
    const float* z   = (const float*)d_in[0];
    const float* u   = (const float*)d_in[1];
    const float* xp  = (const float*)d_in[2];
    const float* Pp  = (const float*)d_in[3];
    const float* qld = (const float*)d_in[4];
    const float* qod = (const float*)d_in[5];
    const float* rld = (const float*)d_in[6];
    const float* rod = (const float*)d_in[7];

    int B = in_sizes[0] / 3;
    float* out_x = (float*)d_out;
    float* out_P = out_x + (size_t)B * 6;

    int ntot = (B + TPB - 1) / TPB;
    int grid = 608;                 // 4 CTAs/SM x 152 SMs (GB300)
    if (grid > ntot) grid = ntot;

    ekf_kernel<<<grid, TPB>>>(z, u, xp, Pp, qld, qod, rld, rod, out_x, out_P, B);
}

// round 5
// speedup vs baseline: 1.3226x; 1.0183x over previous
#include <cuda_runtime.h>
#include <cstdint>

#define DT_C 0.02f
#define GRAV_C 10.0f
#define THRUST_C 6.0f
#define TORQUE_C 1.0f
#define TPB 128

__device__ __forceinline__ void cp_async16(uint32_t smem_dst, const void* gmem_src) {
    asm volatile("cp.async.cg.shared.global [%0], [%1], 16;"
                 :: "r"(smem_dst), "l"(gmem_src) : "memory");
}
__device__ __forceinline__ void cp_commit() {
    asm volatile("cp.async.commit_group;" ::: "memory");
}

__global__ __launch_bounds__(TPB, 6)
void ekf_kernel(const float* __restrict__ z, const float* __restrict__ u,
                const float* __restrict__ xprev, const float* __restrict__ Pprev,
                const float* __restrict__ qld, const float* __restrict__ qod,
                const float* __restrict__ rld, const float* __restrict__ rod,
                float* __restrict__ out_x, float* __restrict__ out_P, int B) {
    __shared__ float4 sP[2][TPB * 9];   // 36864 B
    __shared__ float sQ[36];
    __shared__ float sR[9];

    const int t = threadIdx.x;
    const int G = gridDim.x;
    const int bid = blockIdx.x;
    const int ntot = (B + TPB - 1) / TPB;
    const int nt = (ntot > bid) ? ((ntot - bid + G - 1) / G) : 0;

    // ---- Build Q = L L^T + 1e-6 I (threads 0..35) and R (36..44), once per CTA ----
    if (t < 36) {
        int i = t / 6, j = t % 6;
        float acc = (i == j) ? 1e-6f : 0.0f;
        #pragma unroll
        for (int k = 0; k < 6; k++) {
            float Lik = (k < i) ? qod[i * (i - 1) / 2 + k] : ((k == i) ? expf(qld[i]) : 0.0f);
            float Ljk = (k < j) ? qod[j * (j - 1) / 2 + k] : ((k == j) ? expf(qld[j]) : 0.0f);
            acc += Lik * Ljk;
        }
        sQ[t] = acc;
    } else if (t < 45) {
        int t2 = t - 36;
        int i = t2 / 3, j = t2 % 3;
        float acc = (i == j) ? 1e-6f : 0.0f;
        #pragma unroll
        for (int k = 0; k < 3; k++) {
            float Lik = (k < i) ? rod[i * (i - 1) / 2 + k] : ((k == i) ? expf(rld[i]) : 0.0f);
            float Ljk = (k < j) ? rod[j * (j - 1) / 2 + k] : ((k == j) ? expf(rld[j]) : 0.0f);
            acc += Lik * Ljk;
        }
        sR[t2] = acc;
    }

    if (nt == 0) return;

    auto issue_tile = [&](int k, int p) {
        int tile = bid + k * G;
        size_t base = (size_t)tile * TPB;
        if (base + TPB <= (size_t)B) {   // full tile: coalesced P staging
            const float4* Pg = reinterpret_cast<const float4*>(Pprev) + base * 9;
            uint32_t sb = (uint32_t)__cvta_generic_to_shared(&sP[p][0]);
            #pragma unroll
            for (int kk = 0; kk < 9; kk++)
                cp_async16(sb + (uint32_t)(t + kk * TPB) * 16u, Pg + t + kk * TPB);
        }
    };

    // ---- Prologue: prefetch first two tiles ----
    issue_tile(0, 0);
    cp_commit();
    if (nt > 1) issue_tile(1, 1);
    cp_commit();   // possibly empty; positional wait keeps group numbering consistent

    for (int k = 0; k < nt; k++) {
        int p = k & 1;
        int tile = bid + k * G;
        size_t base = (size_t)tile * TPB;
        bool full = (base + TPB <= (size_t)B);
        int b = (int)base + t;
        bool active = (b < B);

        // ---- Direct small loads (issued before the pipeline wait; overlap) ----
        float px = 0, py = 0, vx = 0, vy = 0, th = 0, om = 0;
        float u0 = 0, u1 = 0, z0 = 0, z1 = 0, z2 = 0;
        if (active) {
            const float2* x2 = reinterpret_cast<const float2*>(xprev + (size_t)b * 6);
            float2 a = x2[0], bb = x2[1], cc = x2[2];
            px = a.x; py = a.y; vx = bb.x; vy = bb.y; th = cc.x; om = cc.y;
            float2 uu = reinterpret_cast<const float2*>(u)[b];
            u0 = uu.x; u1 = uu.y;
            z0 = z[(size_t)b * 3 + 0];
            z1 = z[(size_t)b * 3 + 1];
            z2 = z[(size_t)b * 3 + 2];
        }

        // ---- Dynamics + Jacobian coefficients (independent of P; hides wait) ----
        float mp = fminf(fmaxf(u0, 0.0f), 1.0f);
        float s, c;
        __sincosf(th, &s, &c);
        float Tm = THRUST_C * mp;
        float nvx = vx + (-Tm * s) * DT_C;
        float nvy = vy + (Tm * c - GRAV_C) * DT_C;
        float nom = om + (TORQUE_C * u1) * DT_C;
        float npx = px + nvx * DT_C;
        float npy = py + nvy * DT_C;
        float nth = th + nom * DT_C;

        float a2 = -Tm * c * DT_C;   // F[2][4]
        float a3 = -Tm * s * DT_C;   // F[3][4]
        float a0 = a2 * DT_C;        // F[0][4]
        float a1 = a3 * DT_C;        // F[1][4]

        if (k + 1 < nt) asm volatile("cp.async.wait_group 1;" ::: "memory");
        else            asm volatile("cp.async.wait_group 0;" ::: "memory");
        __syncthreads();

        // ---- Fetch my P_prev ----
        float Pf[36];
        if (full) {
            #pragma unroll
            for (int i = 0; i < 9; i++) {
                float4 v = sP[p][t * 9 + i];
                Pf[4 * i + 0] = v.x; Pf[4 * i + 1] = v.y;
                Pf[4 * i + 2] = v.z; Pf[4 * i + 3] = v.w;
            }
        } else if (active) {
            const float4* p4 = reinterpret_cast<const float4*>(Pprev + (size_t)b * 36);
            #pragma unroll
            for (int i = 0; i < 9; i++) {
                float4 v = p4[i];
                Pf[4 * i + 0] = v.x; Pf[4 * i + 1] = v.y;
                Pf[4 * i + 2] = v.z; Pf[4 * i + 3] = v.w;
            }
        } else {
            #pragma unroll
            for (int i = 0; i < 36; i++) Pf[i] = 0.0f;
        }
#define Pm(i, j) Pf[(i) * 6 + (j)]

        // ---- P_pred = F P F^T + Q (sparse F: row ops then col ops, in place) ----
        #pragma unroll
        for (int j = 0; j < 6; j++) {
            Pm(0, j) += DT_C * Pm(2, j) + a0 * Pm(4, j);
            Pm(1, j) += DT_C * Pm(3, j) + a1 * Pm(4, j);
            Pm(2, j) += a2 * Pm(4, j);
            Pm(3, j) += a3 * Pm(4, j);
            Pm(4, j) += DT_C * Pm(5, j);
        }
        #pragma unroll
        for (int i = 0; i < 6; i++) {
            Pm(i, 0) += DT_C * Pm(i, 2) + a0 * Pm(i, 4);
            Pm(i, 1) += DT_C * Pm(i, 3) + a1 * Pm(i, 4);
            Pm(i, 2) += a2 * Pm(i, 4);
            Pm(i, 3) += a3 * Pm(i, 4);
            Pm(i, 4) += DT_C * Pm(i, 5);
        }

        // ---- Upper triangle of P_pred + Q ----
        float up[21];
        {
            int kk = 0;
            #pragma unroll
            for (int i = 0; i < 6; i++)
                #pragma unroll
                for (int j = i; j < 6; j++) {
                    up[kk] = Pm(i, j) + sQ[i * 6 + j];
                    kk++;
                }
        }
#undef Pm
#define UIDX(i, j) ((i) * 6 - (i) * ((i) + 1) / 2 + (j))
#define US(i, j) ((i) <= (j) ? up[UIDX(i, j)] : up[UIDX(j, i)])

        // ---- S = P_pred[(0,1,4),(0,1,4)] + R ; symmetric 3x3 inverse ----
        float S00 = US(0, 0) + sR[0];
        float S01 = US(0, 1) + sR[1];
        float S02 = US(0, 4) + sR[2];
        float S11 = US(1, 1) + sR[4];
        float S12 = US(1, 4) + sR[5];
        float S22 = US(4, 4) + sR[8];

        float i00 = S11 * S22 - S12 * S12;
        float i01 = S02 * S12 - S01 * S22;
        float i02 = S01 * S12 - S02 * S11;
        float i11 = S00 * S22 - S02 * S02;
        float i12 = S01 * S02 - S00 * S12;
        float i22 = S00 * S11 - S01 * S01;
        float invdet = 1.0f / (S00 * i00 + S01 * i01 + S02 * i02);
        i00 *= invdet; i01 *= invdet; i02 *= invdet;
        i11 *= invdet; i12 *= invdet; i22 *= invdet;

        // ---- K[k] = Si * (P[0][k], P[1][k], P[4][k]) ----
        float K[6][3];
        #pragma unroll
        for (int kk = 0; kk < 6; kk++) {
            float h0 = US(0, kk), h1 = US(1, kk), h2 = US(4, kk);
            K[kk][0] = h0 * i00 + h1 * i01 + h2 * i02;
            K[kk][1] = h0 * i01 + h1 * i11 + h2 * i12;
            K[kk][2] = h0 * i02 + h1 * i12 + h2 * i22;
        }

        // ---- x_upd (direct store, float2) ----
        float y0 = z0 - npx, y1 = z1 - npy, y2 = z2 - nth;
        if (active) {
            float xpred[6] = {npx, npy, nvx, nvy, nth, nom};
            float2* ox2 = reinterpret_cast<float2*>(out_x + (size_t)b * 6);
            #pragma unroll
            for (int i = 0; i < 3; i++) {
                float v0 = xpred[2 * i]     + K[2 * i][0] * y0 + K[2 * i][1] * y1 + K[2 * i][2] * y2;
                float v1 = xpred[2 * i + 1] + K[2 * i + 1][0] * y0 + K[2 * i + 1][1] * y1 + K[2 * i + 1][2] * y2;
                ox2[i] = make_float2(v0, v1);
            }
        }

        // ---- P_upd = P_pred - K (H P_pred), symmetric ----
        float Pu[36];
        #pragma unroll
        for (int i = 0; i < 6; i++)
            #pragma unroll
            for (int j = i; j < 6; j++) {
                float v = US(i, j)
                    - K[i][0] * US(0, j) - K[i][1] * US(1, j) - K[i][2] * US(4, j);
                Pu[i * 6 + j] = v;
                Pu[j * 6 + i] = v;
            }
#undef US
#undef UIDX

        // ---- P store ----
        if (full) {
            // stage into the just-consumed buffer (per-thread region), then coalesced STG
            #pragma unroll
            for (int i = 0; i < 9; i++)
                sP[p][t * 9 + i] = make_float4(Pu[4 * i], Pu[4 * i + 1], Pu[4 * i + 2], Pu[4 * i + 3]);
            __syncthreads();
            float4* Po = reinterpret_cast<float4*>(out_P) + base * 9;
            #pragma unroll
            for (int kk = 0; kk < 9; kk++)
                Po[t + kk * TPB] = sP[p][t + kk * TPB];
            __syncthreads();   // LDS-for-STG done before buffer p is re-prefetched
        } else if (active) {
            float4* op4 = reinterpret_cast<float4*>(out_P + (size_t)b * 36);
            #pragma unroll
            for (int i = 0; i < 9; i++)
                op4[i] = make_float4(Pu[4 * i], Pu[4 * i + 1], Pu[4 * i + 2], Pu[4 * i + 3]);
        }

        // ---- Prefetch tile k+2 into buffer p ----
        if (k + 2 < nt) issue_tile(k + 2, p);
        cp_commit();
    }
}

extern "C" void kernel_launch(void* const* d_in, const int* in_sizes, int n_in,
                              void* d_out, int out_size) {
    const float* z   = (const float*)d_in[0];
    const float* u   = (const float*)d_in[1];
    const float* xp  = (const float*)d_in[2];
    const float* Pp  = (const float*)d_in[3];
    const float* qld = (const float*)d_in[4];
    const float* qod = (const float*)d_in[5];
    const float* rld = (const float*)d_in[6];
    const float* rod = (const float*)d_in[7];

    int B = in_sizes[0] / 3;
    float* out_x = (float*)d_out;
    float* out_P = out_x + (size_t)B * 6;

    int ntot = (B + TPB - 1) / TPB;
    int grid = 912;                 // 6 CTAs/SM x 152 SMs, all resident in wave 1
    if (grid > ntot) grid = ntot;

    ekf_kernel<<<grid, TPB>>>(z, u, xp, Pp, qld, qod, rld, rod, out_x, out_P, B);
}